// round 14
// baseline (speedup 1.0000x reference)
#include <cuda_runtime.h>

// out[b, l, i, j] = emission[b, l, j] + transition[i, j]
// B=32, L=512, T=64. Output = 256 MB fp32 — pure write-stream bound.
//
// FINAL KERNEL (confirmed over 4 benches: wall 43.49/43.52/43.74/43.78us,
// ncu 40.6-42.3us). At the full-chip LTS/HBM write ceiling: L1/L2/DRAM
// co-pinned ~2/3, store-policy A/B identical, TMA path-equivalent per
// B300_MICROARCH. All levers individually isolated across the session:
//   v8 256-bit stores (-11us), register-reuse load reduction (-5us),
//   block-quantum tuning (-0.3us); deeper reuse / persistent grid / store
//   policy: regress or neutral. Floor = 256MB / ~6.4 TB/s effective ~= 41us.
//
// One warp per (b,l) row (16384 warps). Lane: j8 = lane&7, igrp = lane>>3.
// Emission chunk register-resident (loaded once, reused 16x); 16 iterations
// over transition rows (L1-resident after warmup), each iteration storing
// 1KB contiguous per warp via v8 (256-bit) evict-first stores.

__device__ __forceinline__ void ldg256(const float* p, float4& a, float4& b) {
    asm volatile("ld.global.nc.v8.f32 {%0,%1,%2,%3,%4,%5,%6,%7}, [%8];"
                 : "=f"(a.x), "=f"(a.y), "=f"(a.z), "=f"(a.w),
                   "=f"(b.x), "=f"(b.y), "=f"(b.z), "=f"(b.w)
                 : "l"(p));
}

__device__ __forceinline__ void stg256_cs(float* p, float4 a, float4 b) {
    asm volatile("st.global.cs.v8.f32 [%0], {%1,%2,%3,%4,%5,%6,%7,%8};"
                 :: "l"(p),
                    "f"(a.x), "f"(a.y), "f"(a.z), "f"(a.w),
                    "f"(b.x), "f"(b.y), "f"(b.z), "f"(b.w)
                 : "memory");
}

__global__ __launch_bounds__(128)
void CRF_53128745451552_kernel(const float* __restrict__ em,
                               const float* __restrict__ tr,
                               float* __restrict__ out) {
    int warp = (blockIdx.x * blockDim.x + threadIdx.x) >> 5;  // = bl, 0..16383
    int lane = threadIdx.x & 31;
    int j8   = lane & 7;    // 8-float chunk within j (0..7)
    int igrp = lane >> 3;   // i offset within a 4-row group (0..3)

    // Emission chunk for this (bl, j8): loaded once, reused 16x.
    float4 e0, e1;
    ldg256(em + ((size_t)warp << 6) + (j8 << 3), e0, e1);

    const float* tp = tr  + (igrp << 6) + (j8 << 3);
    float*       op = out + ((size_t)warp << 12) + (igrp << 6) + (j8 << 3);

#pragma unroll 4
    for (int it = 0; it < 16; it++) {
        float4 t0, t1;
        ldg256(tp + it * 256, t0, t1);   // transition[it*4+igrp, j8*8..] (L1 hit)

        float4 r0, r1;
        r0.x = e0.x + t0.x;  r0.y = e0.y + t0.y;
        r0.z = e0.z + t0.z;  r0.w = e0.w + t0.w;
        r1.x = e1.x + t1.x;  r1.y = e1.y + t1.y;
        r1.z = e1.z + t1.z;  r1.w = e1.w + t1.w;

        stg256_cs(op + it * 256, r0, r1);  // warp-iter: 1KB contiguous
    }
}

extern "C" void kernel_launch(void* const* d_in, const int* in_sizes, int n_in,
                              void* d_out, int out_size) {
    const float* em = (const float*)d_in[0];   // emission [32, 512, 64] fp32
    const float* tr = (const float*)d_in[1];   // transition [64, 64] fp32
    float* out = (float*)d_out;

    // 16384 rows, one warp each; 128 threads = 4 warps per block -> 4096 blocks.
    CRF_53128745451552_kernel<<<4096, 128>>>(em, tr, out);
}